// round 14
// baseline (speedup 1.0000x reference)
#include <cuda_runtime.h>
#include <cuda_bf16.h>
#include <cuda_fp16.h>
#include <cstdint>

#define NSAMP 4096
typedef unsigned long long u64;
typedef unsigned int u32;
typedef unsigned short u16;

// ---------------- split + mma + ldmatrix helpers ----------------
__device__ __forceinline__ void bsplit(float x, u16* h, u16* l) {
    __nv_bfloat16 hh = __float2bfloat16_rn(x);
    *h = __bfloat16_as_ushort(hh);
    *l = __bfloat16_as_ushort(__float2bfloat16_rn(x - __bfloat162float(hh)));
}
__device__ __forceinline__ void hsplit(float x, u16* h, u16* l) {
    __half hh = __float2half_rn(x);
    *h = __half_as_ushort(hh);
    *l = __half_as_ushort(__float2half_rn(x - __half2float(hh)));
}
__device__ __forceinline__ void mma_bf16(float* d, const u32* a, u32 b0, u32 b1) {
    asm("mma.sync.aligned.m16n8k16.row.col.f32.bf16.bf16.f32 "
        "{%0,%1,%2,%3},{%4,%5,%6,%7},{%8,%9},{%0,%1,%2,%3};"
        : "+f"(d[0]), "+f"(d[1]), "+f"(d[2]), "+f"(d[3])
        : "r"(a[0]), "r"(a[1]), "r"(a[2]), "r"(a[3]), "r"(b0), "r"(b1));
}
__device__ __forceinline__ void mma_f16(float* d, const u32* a, u32 b0, u32 b1) {
    asm("mma.sync.aligned.m16n8k16.row.col.f32.f16.f16.f32 "
        "{%0,%1,%2,%3},{%4,%5,%6,%7},{%8,%9},{%0,%1,%2,%3};"
        : "+f"(d[0]), "+f"(d[1]), "+f"(d[2]), "+f"(d[3])
        : "r"(a[0]), "r"(a[1]), "r"(a[2]), "r"(a[3]), "r"(b0), "r"(b1));
}
__device__ __forceinline__ void ldsm4(u32* r, u32 addr) {
    asm volatile("ldmatrix.sync.aligned.m8n8.x4.shared.b16 {%0,%1,%2,%3}, [%4];"
                 : "=r"(r[0]), "=r"(r[1]), "=r"(r[2]), "=r"(r[3]) : "r"(addr));
}
__device__ __forceinline__ u32 smem_u32(const void* p) {
    u32 a; asm("{ .reg .u64 t; cvta.to.shared.u64 t, %1; cvt.u32.u64 %0, t; }" : "=r"(a) : "l"(p));
    return a;
}

// ---------------- scratch ----------------
__device__ uint4 g_w1ph[896],  g_w1pl[896];
__device__ uint4 g_w2ph[5120], g_w2pl[5120];
__device__ uint4 g_w3ph[12288], g_w3pl[12288];
__device__ float g_feat[(size_t)NSAMP * 256];
__device__ u16   g_zh[(size_t)NSAMP * 128];
__device__ u16   g_zl[(size_t)NSAMP * 128];
__device__ float g_sq[NSAMP];
__device__ float g_fcwT[256 * 128];

// ---------------- weight prep: fragment-order packing ----------------
__global__ void k_prep_w1(const float* __restrict__ w1) {
    int idx = blockIdx.x * blockDim.x + threadIdx.x;
    if (idx >= 896) return;
    int lane = idx & 31, mt = (idx >> 5) & 3, kt = idx >> 7;
    int g = lane >> 2, tc = lane & 3;
    int m = mt * 16 + g, c = kt * 16 + 2 * tc;
    int rows[4] = {m, m + 8, m, m + 8};
    int cols[4] = {c, c, c + 8, c + 8};
    u32 hq[4], lq[4];
#pragma unroll
    for (int i = 0; i < 4; i++) {
        u16 h0 = 0, l0 = 0, h1 = 0, l1 = 0;
        if (cols[i] < 100)     bsplit(w1[rows[i] * 100 + cols[i]], &h0, &l0);
        if (cols[i] + 1 < 100) bsplit(w1[rows[i] * 100 + cols[i] + 1], &h1, &l1);
        hq[i] = (u32)h0 | ((u32)h1 << 16);
        lq[i] = (u32)l0 | ((u32)l1 << 16);
    }
    g_w1ph[idx] = make_uint4(hq[0], hq[1], hq[2], hq[3]);
    g_w1pl[idx] = make_uint4(lq[0], lq[1], lq[2], lq[3]);
}
__global__ void k_prep_w2(const float* __restrict__ w2) {
    int idx = blockIdx.x * blockDim.x + threadIdx.x;
    if (idx >= 5120) return;
    int lane = idx & 31, mt = (idx >> 5) & 7, kt = (idx >> 8) & 3, s = idx >> 10;
    int g = lane >> 2, tc = lane & 3;
    int m = mt * 16 + g, c = kt * 16 + 2 * tc;
    int rows[4] = {m, m + 8, m, m + 8};
    int cols[4] = {c, c, c + 8, c + 8};
    u32 hq[4], lq[4];
#pragma unroll
    for (int i = 0; i < 4; i++) {
        u16 h0, l0, h1, l1;
        bsplit(w2[rows[i] * 320 + cols[i] * 5 + s], &h0, &l0);
        bsplit(w2[rows[i] * 320 + (cols[i] + 1) * 5 + s], &h1, &l1);
        hq[i] = (u32)h0 | ((u32)h1 << 16);
        lq[i] = (u32)l0 | ((u32)l1 << 16);
    }
    g_w2ph[idx] = make_uint4(hq[0], hq[1], hq[2], hq[3]);
    g_w2pl[idx] = make_uint4(lq[0], lq[1], lq[2], lq[3]);
}
__global__ void k_prep_w3(const float* __restrict__ w3) {
    int idx = blockIdx.x * blockDim.x + threadIdx.x;
    if (idx >= 12288) return;
    int lane = idx & 31, mt = (idx >> 5) & 15, kt = (idx >> 9) & 7, s = idx >> 12;
    int g = lane >> 2, tc = lane & 3;
    int m = mt * 16 + g, c = kt * 16 + 2 * tc;
    int rows[4] = {m, m + 8, m, m + 8};
    int cols[4] = {c, c, c + 8, c + 8};
    u32 hq[4], lq[4];
#pragma unroll
    for (int i = 0; i < 4; i++) {
        u16 h0, l0, h1, l1;
        bsplit(w3[rows[i] * 384 + cols[i] * 3 + s], &h0, &l0);
        bsplit(w3[rows[i] * 384 + (cols[i] + 1) * 3 + s], &h1, &l1);
        hq[i] = (u32)h0 | ((u32)h1 << 16);
        lq[i] = (u32)l0 | ((u32)l1 << 16);
    }
    g_w3ph[idx] = make_uint4(hq[0], hq[1], hq[2], hq[3]);
    g_w3pl[idx] = make_uint4(lq[0], lq[1], lq[2], lq[3]);
}

// ---------------- fully fused conv1 -> conv2 -> conv3 (+ pool + mean) ----------------
// smem layout (bytes):
//   X2:   @0        2 planes x [260 rows x 144 B]           = 74,880
//   B1:   @74,880   2 planes x [256 rows x 240 B]           = 122,880 (conv1 only)
//   X3:   @74,880   2 planes x [130 rows x 272 B]           = 70,720  (after conv1)
//   xs:   @197,760  2 planes x 612 u16 (1232 B each)        = 2,464
#define F_X2L 37440
#define F_B1OFF 74880
#define F_B1L 61440
#define F_X3OFF 74880
#define F_X3L 35360
#define F_XSOFF 197760
#define F_SMEM (197760 + 2464)
__global__ void __launch_bounds__(512) k_c123(const float* __restrict__ x,
                                              const float* __restrict__ b1,
                                              const float* __restrict__ b2,
                                              const float* __restrict__ b3) {
    extern __shared__ __align__(16) char fsm[];
    u16* X2h = (u16*)fsm;
    u16* X2l = (u16*)(fsm + F_X2L);
    u16* B1h = (u16*)(fsm + F_B1OFF);
    u16* X3h = (u16*)(fsm + F_X3OFF);
    u16* X3l = (u16*)(fsm + F_X3OFF + F_X3L);
    u16* xh_s = (u16*)(fsm + F_XSOFF);
    u16* xl_s = (u16*)(fsm + F_XSOFF + 1232);
    const int n = blockIdx.x;
    const int tid = threadIdx.x;  // 512
    const int lane = tid & 31, wp = tid >> 5;
    const int q = lane >> 3, rr = lane & 7;
    const int g2 = lane >> 2, tc = lane & 3;
    const float* xn = x + (size_t)n * 512;

    // ---- stage split x[-49..561], zero X2 pad rows 0,1,258,259 ----
    for (int i = tid; i < 611; i += 512) {
        int j = i - 49;
        float v = (j >= 0 && j < 512) ? xn[j] : 0.f;
        u16 h, l; bsplit(v, &h, &l);
        xh_s[i] = h; xl_s[i] = l;
    }
    for (int i = tid; i < 288; i += 512) {
        int pl = i / 144, rem = i % 144;
        int rr2 = rem / 36;
        int row = (rr2 < 2) ? rr2 : 256 + rr2;   // 0,1,258,259
        int cw = rem % 36;
        *(u32*)(fsm + pl * F_X2L + row * 144 + cw * 4) = 0u;
    }
    __syncthreads();

    // ================= conv1: two half-tiles =================
    float acc1[8][4];
    for (int h = 0; h < 2; h++) {
        // build B tile: 256 rows x 120 u16 (cols 0..99 data, 100..119 zero)
        for (int idx = tid; idx < 15360; idx += 512) {
            int row = idx / 60, kp = idx % 60;
            u32 vh = 0, vl = 0;
            if (kp < 50) {
                int base = 256 * h + row + 2 * kp;
                vh = (u32)xh_s[base] | ((u32)xh_s[base + 1] << 16);
                vl = (u32)xl_s[base] | ((u32)xl_s[base + 1] << 16);
            }
            *(u32*)((char*)B1h + row * 240 + 4 * kp) = vh;
            *(u32*)((char*)B1h + F_B1L + row * 240 + 4 * kp) = vl;
        }
        __syncthreads();

        const int mt = wp >> 2, nq = wp & 3;
        const int rowq = nq * 64 + 8 * (q >> 1) + rr;
        const u32 bA = smem_u32(B1h);
#pragma unroll
        for (int j = 0; j < 8; j++) { acc1[j][0] = acc1[j][1] = acc1[j][2] = acc1[j][3] = 0.f; }

#pragma unroll
        for (int kt = 0; kt < 7; kt++) {
            const u32 colb = (u32)(kt * 32 + (q & 1) * 16);
            const uint4 Ah = g_w1ph[(kt * 4 + mt) * 32 + lane];
            const uint4 Al = g_w1pl[(kt * 4 + mt) * 32 + lane];
#pragma unroll
            for (int jp = 0; jp < 4; jp++) {
                u32 ad = bA + (u32)(rowq + jp * 16) * 240u + colb;
                u32 Bh_[4], Bl_[4];
                ldsm4(Bh_, ad);
                ldsm4(Bl_, ad + F_B1L);
                mma_bf16(acc1[2 * jp],     (const u32*)&Ah, Bh_[0], Bh_[1]);
                mma_bf16(acc1[2 * jp],     (const u32*)&Ah, Bl_[0], Bl_[1]);
                mma_bf16(acc1[2 * jp],     (const u32*)&Al, Bh_[0], Bh_[1]);
                mma_bf16(acc1[2 * jp + 1], (const u32*)&Ah, Bh_[2], Bh_[3]);
                mma_bf16(acc1[2 * jp + 1], (const u32*)&Ah, Bl_[2], Bl_[3]);
                mma_bf16(acc1[2 * jp + 1], (const u32*)&Al, Bh_[2], Bh_[3]);
            }
        }

        // epilogue: pooled+relu -> directly into X2 rows (global pp + 2)
        const float bi0 = b1[mt * 16 + g2], bi1 = b1[mt * 16 + g2 + 8];
#pragma unroll
        for (int jj = 0; jj < 8; jj++) {
            int row = 128 * h + nq * 32 + 4 * jj + tc + 2;
            float v0 = fmaxf(fmaxf(acc1[jj][0] + bi0, acc1[jj][1] + bi0), 0.f);
            float v1 = fmaxf(fmaxf(acc1[jj][2] + bi1, acc1[jj][3] + bi1), 0.f);
            u16 hh, ll;
            bsplit(v0, &hh, &ll);
            X2h[row * 72 + mt * 16 + g2] = hh;
            X2l[row * 72 + mt * 16 + g2] = ll;
            bsplit(v1, &hh, &ll);
            X2h[row * 72 + mt * 16 + g2 + 8] = hh;
            X2l[row * 72 + mt * 16 + g2 + 8] = ll;
        }
        __syncthreads();  // B free for rebuild / X3 reuse
    }

    // zero X3 pad rows 0 and 129 (both planes)
    for (int i = tid; i < 272; i += 512) {
        int pl = i / 136, rem = i % 136;
        int row = (rem >= 68) ? 129 : 0;
        int w = rem % 68;
        *(u32*)((char*)X3h + pl * F_X3L + row * 272 + w * 4) = 0u;
    }
    // no sync needed yet: X3 pads not read until after next syncthreads

    // ================= conv2 =================
    const int mp = wp >> 2, nh = (wp >> 1) & 1, jb = wp & 1;
    const int n0 = nh * 128, jbase = jb * 8;
    const u32 xhA = smem_u32(X2h);
    const int rowq = n0 + 8 * jbase + 8 * (q >> 1) + rr;

    float acc[2][8][4];
#pragma unroll
    for (int m = 0; m < 2; m++)
#pragma unroll
        for (int j = 0; j < 8; j++) { acc[m][j][0] = acc[m][j][1] = acc[m][j][2] = acc[m][j][3] = 0.f; }

    for (int s = 0; s < 5; s++) {
        const u32 rbyte = (u32)(rowq + s) * 144u;
#pragma unroll
        for (int kt = 0; kt < 4; kt++) {
            const u32 colb = (u32)(kt * 32 + (q & 1) * 16);
            const uint4 AhA = g_w2ph[(s * 4 + kt) * 256 + (2 * mp) * 32 + lane];
            const uint4 AlA = g_w2pl[(s * 4 + kt) * 256 + (2 * mp) * 32 + lane];
            const uint4 AhB = g_w2ph[(s * 4 + kt) * 256 + (2 * mp + 1) * 32 + lane];
            const uint4 AlB = g_w2pl[(s * 4 + kt) * 256 + (2 * mp + 1) * 32 + lane];
#pragma unroll
            for (int jp = 0; jp < 4; jp++) {
                u32 ad = xhA + rbyte + (u32)(jp * 2304) + colb;
                u32 Bh_[4], Bl_[4];
                ldsm4(Bh_, ad);
                ldsm4(Bl_, ad + F_X2L);
                mma_bf16(acc[0][2 * jp],     (const u32*)&AhA, Bh_[0], Bh_[1]);
                mma_bf16(acc[0][2 * jp],     (const u32*)&AhA, Bl_[0], Bl_[1]);
                mma_bf16(acc[0][2 * jp],     (const u32*)&AlA, Bh_[0], Bh_[1]);
                mma_bf16(acc[0][2 * jp + 1], (const u32*)&AhA, Bh_[2], Bh_[3]);
                mma_bf16(acc[0][2 * jp + 1], (const u32*)&AhA, Bl_[2], Bl_[3]);
                mma_bf16(acc[0][2 * jp + 1], (const u32*)&AlA, Bh_[2], Bh_[3]);
                mma_bf16(acc[1][2 * jp],     (const u32*)&AhB, Bh_[0], Bh_[1]);
                mma_bf16(acc[1][2 * jp],     (const u32*)&AhB, Bl_[0], Bl_[1]);
                mma_bf16(acc[1][2 * jp],     (const u32*)&AlB, Bh_[0], Bh_[1]);
                mma_bf16(acc[1][2 * jp + 1], (const u32*)&AhB, Bh_[2], Bh_[3]);
                mma_bf16(acc[1][2 * jp + 1], (const u32*)&AhB, Bl_[2], Bl_[3]);
                mma_bf16(acc[1][2 * jp + 1], (const u32*)&AlB, Bh_[2], Bh_[3]);
            }
        }
    }

    // conv2 epilogue -> X3 rows pp+1
#pragma unroll
    for (int m = 0; m < 2; m++) {
        const int m0 = mp * 32 + m * 16;
        const float bi0 = b2[m0 + g2], bi1 = b2[m0 + g2 + 8];
#pragma unroll
        for (int jl = 0; jl < 8; jl++) {
            int pp = n0 / 2 + 4 * (jbase + jl) + tc;
            float v0 = fmaxf(fmaxf(acc[m][jl][0] + bi0, acc[m][jl][1] + bi0), 0.f);
            float v1 = fmaxf(fmaxf(acc[m][jl][2] + bi1, acc[m][jl][3] + bi1), 0.f);
            u16 h, l;
            bsplit(v0, &h, &l);
            X3h[(pp + 1) * 136 + m0 + g2] = h; X3l[(pp + 1) * 136 + m0 + g2] = l;
            bsplit(v1, &h, &l);
            X3h[(pp + 1) * 136 + m0 + g2 + 8] = h; X3l[(pp + 1) * 136 + m0 + g2 + 8] = l;
        }
    }
    __syncthreads();

    // ================= conv3 =================
    const int mp3 = wp >> 1, jb3 = wp & 1;
    const int jbase3 = jb3 * 8;
    const u32 x3A = smem_u32(X3h);
    const int rowq3 = 8 * jbase3 + 8 * (q >> 1) + rr;

#pragma unroll
    for (int m = 0; m < 2; m++)
#pragma unroll
        for (int j = 0; j < 8; j++) { acc[m][j][0] = acc[m][j][1] = acc[m][j][2] = acc[m][j][3] = 0.f; }

    for (int s = 0; s < 3; s++) {
        const u32 rbyte = (u32)(rowq3 + s) * 272u;
#pragma unroll
        for (int kt = 0; kt < 8; kt++) {
            const u32 colb = (u32)(kt * 32 + (q & 1) * 16);
            const uint4 AhA = g_w3ph[(s * 8 + kt) * 512 + (2 * mp3) * 32 + lane];
            const uint4 AlA = g_w3pl[(s * 8 + kt) * 512 + (2 * mp3) * 32 + lane];
            const uint4 AhB = g_w3ph[(s * 8 + kt) * 512 + (2 * mp3 + 1) * 32 + lane];
            const uint4 AlB = g_w3pl[(s * 8 + kt) * 512 + (2 * mp3 + 1) * 32 + lane];
#pragma unroll
            for (int jp = 0; jp < 4; jp++) {
                u32 ad = x3A + rbyte + (u32)(jp * 4352) + colb;
                u32 Bh_[4], Bl_[4];
                ldsm4(Bh_, ad);
                ldsm4(Bl_, ad + F_X3L);
                mma_bf16(acc[0][2 * jp],     (const u32*)&AhA, Bh_[0], Bh_[1]);
                mma_bf16(acc[0][2 * jp],     (const u32*)&AhA, Bl_[0], Bl_[1]);
                mma_bf16(acc[0][2 * jp],     (const u32*)&AlA, Bh_[0], Bh_[1]);
                mma_bf16(acc[0][2 * jp + 1], (const u32*)&AhA, Bh_[2], Bh_[3]);
                mma_bf16(acc[0][2 * jp + 1], (const u32*)&AhA, Bl_[2], Bl_[3]);
                mma_bf16(acc[0][2 * jp + 1], (const u32*)&AlA, Bh_[2], Bh_[3]);
                mma_bf16(acc[1][2 * jp],     (const u32*)&AhB, Bh_[0], Bh_[1]);
                mma_bf16(acc[1][2 * jp],     (const u32*)&AhB, Bl_[0], Bl_[1]);
                mma_bf16(acc[1][2 * jp],     (const u32*)&AlB, Bh_[0], Bh_[1]);
                mma_bf16(acc[1][2 * jp + 1], (const u32*)&AhB, Bh_[2], Bh_[3]);
                mma_bf16(acc[1][2 * jp + 1], (const u32*)&AhB, Bl_[2], Bl_[3]);
                mma_bf16(acc[1][2 * jp + 1], (const u32*)&AlB, Bh_[2], Bh_[3]);
            }
        }
    }
    __syncthreads();  // X3 reads done; reuse smem for partials

    float* part = (float*)fsm;  // [256 oc][2 j-halves]
#pragma unroll
    for (int m = 0; m < 2; m++) {
        const int m0 = mp3 * 32 + m * 16;
        const float bi0 = b3[m0 + g2], bi1 = b3[m0 + g2 + 8];
        float s0 = 0.f, s1 = 0.f;
#pragma unroll
        for (int jl = 0; jl < 8; jl++) {
            float a0 = fmaxf(acc[m][jl][0] + bi0, 0.f);
            float a1 = fmaxf(acc[m][jl][1] + bi0, 0.f);
            s0 += fmaxf(a0, a1);
            float c0 = fmaxf(acc[m][jl][2] + bi1, 0.f);
            float c1 = fmaxf(acc[m][jl][3] + bi1, 0.f);
            s1 += fmaxf(c0, c1);
        }
        s0 += __shfl_xor_sync(0xFFFFFFFFu, s0, 1);
        s0 += __shfl_xor_sync(0xFFFFFFFFu, s0, 2);
        s1 += __shfl_xor_sync(0xFFFFFFFFu, s1, 1);
        s1 += __shfl_xor_sync(0xFFFFFFFFu, s1, 2);
        if (tc == 0) {
            part[(m0 + g2) * 2 + jb3]     = s0;
            part[(m0 + g2 + 8) * 2 + jb3] = s1;
        }
    }
    __syncthreads();
    if (tid < 256) {
        g_feat[(size_t)n * 256 + tid] = (part[2 * tid] + part[2 * tid + 1]) * (1.f / 64.f);
    }
}

// ---------------- fc weight transpose ----------------
__global__ void k_fcT(const float* __restrict__ fcw) {
    int idx = blockIdx.x * blockDim.x + threadIdx.x;
    if (idx < 128 * 256) {
        int j = idx / 256, k = idx % 256;
        g_fcwT[k * 128 + j] = fcw[idx];
    }
}

// ---------------- fc + relu + bn (z -> fp16 split) ----------------
__global__ void k_fc(const float* __restrict__ fcb, const float* __restrict__ gamma,
                     const float* __restrict__ beta, const float* __restrict__ mean,
                     const float* __restrict__ var) {
    const int n = blockIdx.x;
    const int j = threadIdx.x;
    __shared__ float fs[256];
    __shared__ float ps[4];
    fs[j]       = g_feat[(size_t)n * 256 + j];
    fs[j + 128] = g_feat[(size_t)n * 256 + 128 + j];
    __syncthreads();
    float acc = fcb[j];
#pragma unroll 8
    for (int k = 0; k < 256; k++) acc = fmaf(fs[k], g_fcwT[k * 128 + j], acc);
    acc = fmaxf(acc, 0.f);
    float z = gamma[j] * (acc - mean[j]) * rsqrtf(var[j] + 1e-5f) + beta[j];
    u16 zh, zl; hsplit(z, &zh, &zl);
    g_zh[(size_t)n * 128 + j] = zh;
    g_zl[(size_t)n * 128 + j] = zl;
    float s = z * z;
#pragma unroll
    for (int off = 16; off; off >>= 1) s += __shfl_xor_sync(0xFFFFFFFFu, s, off);
    if ((j & 31) == 0) ps[j >> 5] = s;
    __syncthreads();
    if (j == 0) g_sq[n] = ps[0] + ps[1] + ps[2] + ps[3];
}

// ---------------- pairwise (mma.sync fp16 split) ----------------
#define PT_AOFF 34816
#define PT_SMEM (4 * 34816)
__global__ void __launch_bounds__(256) k_pair(const int* __restrict__ info, float* __restrict__ out) {
    extern __shared__ __align__(16) char psm[];
    u16* Ash = (u16*)psm;
    u16* Bsh = (u16*)(psm + 2 * PT_AOFF);
    const int ib = blockIdx.y * 128;
    const int jbb = blockIdx.x * 128;
    const int tid = threadIdx.x;
    const int lane = tid & 31, wp = tid >> 5;

    for (int i = tid; i < 2048; i += 256) {
        int r = i >> 4, c = i & 15;
        *(uint4*)((char*)Ash + r * 272 + c * 16)            = ((const uint4*)(g_zh + (size_t)(ib + r) * 128))[c];
        *(uint4*)((char*)Ash + PT_AOFF + r * 272 + c * 16)  = ((const uint4*)(g_zl + (size_t)(ib + r) * 128))[c];
        *(uint4*)((char*)Bsh + r * 272 + c * 16)            = ((const uint4*)(g_zh + (size_t)(jbb + r) * 128))[c];
        *(uint4*)((char*)Bsh + PT_AOFF + r * 272 + c * 16)  = ((const uint4*)(g_zl + (size_t)(jbb + r) * 128))[c];
    }
    __syncthreads();

    const int mh = wp >> 1, nh = wp & 1;
    const int m0base = 32 * mh, jbase = nh * 8;
    const u32 aA = smem_u32(Ash);
    const u32 bB = smem_u32(Bsh);
    const int jA = lane >> 3, rA = lane & 7;
    const int arow = (jA & 1) * 8 + rA;
    const u32 acol = (u32)((jA >> 1) * 16);
    const int q = lane >> 3, rr = lane & 7;
    const int browq = jbase * 8 + 8 * (q >> 1) + rr;
    const u32 bcol = (u32)((q & 1) * 16);

    float acc[2][8][4];
#pragma unroll
    for (int m = 0; m < 2; m++)
#pragma unroll
        for (int j = 0; j < 8; j++) { acc[m][j][0] = acc[m][j][1] = acc[m][j][2] = acc[m][j][3] = 0.f; }

#pragma unroll
    for (int kt = 0; kt < 8; kt++) {
        u32 Ah_[2][4], Al_[2][4];
#pragma unroll
        for (int mi = 0; mi < 2; mi++) {
            u32 aad = aA + (u32)(m0base + mi * 16 + arow) * 272u + (u32)(kt * 32) + acol;
            ldsm4(Ah_[mi], aad);
            ldsm4(Al_[mi], aad + PT_AOFF);
        }
#pragma unroll
        for (int jp = 0; jp < 4; jp++) {
            u32 bad = bB + (u32)(browq + jp * 16) * 272u + (u32)(kt * 32) + bcol;
            u32 Bh_[4], Bl_[4];
            ldsm4(Bh_, bad);
            ldsm4(Bl_, bad + PT_AOFF);
#pragma unroll
            for (int mi = 0; mi < 2; mi++) {
                mma_f16(acc[mi][2 * jp],     Ah_[mi], Bh_[0], Bh_[1]);
                mma_f16(acc[mi][2 * jp],     Ah_[mi], Bl_[0], Bl_[1]);
                mma_f16(acc[mi][2 * jp],     Al_[mi], Bh_[0], Bh_[1]);
                mma_f16(acc[mi][2 * jp + 1], Ah_[mi], Bh_[2], Bh_[3]);
                mma_f16(acc[mi][2 * jp + 1], Ah_[mi], Bl_[2], Bl_[3]);
                mma_f16(acc[mi][2 * jp + 1], Al_[mi], Bh_[2], Bh_[3]);
            }
        }
    }

    const int g2 = lane >> 2, tc = lane & 3;
#pragma unroll
    for (int mi = 0; mi < 2; mi++) {
#pragma unroll
        for (int rh = 0; rh < 2; rh++) {
            const int i = ib + m0base + mi * 16 + g2 + rh * 8;
            const float sqi = g_sq[i];
            const int wti = info[2 * i], gi = info[2 * i + 1];
#pragma unroll
            for (int jl = 0; jl < 8; jl++) {
                const int j0 = jbb + nh * 64 + 8 * jl + 2 * tc;
                float c0 = acc[mi][jl][2 * rh], c1 = acc[mi][jl][2 * rh + 1];
                float2 res;
                {
                    float d2 = sqi + g_sq[j0] - 2.f * c0;
                    float d = sqrtf(fmaxf(d2, 0.f));
                    bool y = (wti == info[2 * j0]) && (gi == 1) && (info[2 * j0 + 1] == 1);
                    float cl = y ? d : fmaxf(1.f - d, 0.f);
                    res.x = (i == j0) ? 0.f : cl;
                }
                {
                    int j1 = j0 + 1;
                    float d2 = sqi + g_sq[j1] - 2.f * c1;
                    float d = sqrtf(fmaxf(d2, 0.f));
                    bool y = (wti == info[2 * j1]) && (gi == 1) && (info[2 * j1 + 1] == 1);
                    float cl = y ? d : fmaxf(1.f - d, 0.f);
                    res.y = (i == j1) ? 0.f : cl;
                }
                *reinterpret_cast<float2*>(out + (size_t)i * 4096 + j0) = res;
            }
        }
    }
}

// ---------------- launch ----------------
extern "C" void kernel_launch(void* const* d_in, const int* in_sizes, int n_in,
                              void* d_out, int out_size) {
    const float* samples = (const float*)d_in[0];
    const int*   info    = (const int*)d_in[1];
    const float* w1  = (const float*)d_in[2];
    const float* b1  = (const float*)d_in[3];
    const float* w2  = (const float*)d_in[4];
    const float* b2  = (const float*)d_in[5];
    const float* w3  = (const float*)d_in[6];
    const float* b3  = (const float*)d_in[7];
    const float* fcw = (const float*)d_in[8];
    const float* fcb = (const float*)d_in[9];
    const float* gam = (const float*)d_in[10];
    const float* bet = (const float*)d_in[11];
    const float* bmu = (const float*)d_in[12];
    const float* bva = (const float*)d_in[13];
    float* out = (float*)d_out;

    cudaFuncSetAttribute(k_c123, cudaFuncAttributeMaxDynamicSharedMemorySize, F_SMEM);
    cudaFuncSetAttribute(k_pair, cudaFuncAttributeMaxDynamicSharedMemorySize, PT_SMEM);

    k_prep_w1<<<4, 256>>>(w1);
    k_prep_w2<<<20, 256>>>(w2);
    k_prep_w3<<<48, 256>>>(w3);
    k_fcT<<<64, 512>>>(fcw);
    k_c123<<<NSAMP, 512, F_SMEM>>>(samples, b1, b2, b3);
    k_fc<<<NSAMP, 128>>>(fcb, gam, bet, bmu, bva);
    k_pair<<<dim3(32, 32), 256, PT_SMEM>>>(info, out);
}

// round 15
// speedup vs baseline: 1.4401x; 1.4401x over previous
#include <cuda_runtime.h>
#include <cuda_bf16.h>
#include <cuda_fp16.h>
#include <cstdint>

#define NSAMP 4096
typedef unsigned long long u64;
typedef unsigned int u32;
typedef unsigned short u16;

// ---------------- split + mma + ldmatrix helpers ----------------
__device__ __forceinline__ void bsplit(float x, u16* h, u16* l) {
    __nv_bfloat16 hh = __float2bfloat16_rn(x);
    *h = __bfloat16_as_ushort(hh);
    *l = __bfloat16_as_ushort(__float2bfloat16_rn(x - __bfloat162float(hh)));
}
__device__ __forceinline__ void hsplit(float x, u16* h, u16* l) {
    __half hh = __float2half_rn(x);
    *h = __half_as_ushort(hh);
    *l = __half_as_ushort(__float2half_rn(x - __half2float(hh)));
}
__device__ __forceinline__ void mma_bf16(float* d, const u32* a, u32 b0, u32 b1) {
    asm("mma.sync.aligned.m16n8k16.row.col.f32.bf16.bf16.f32 "
        "{%0,%1,%2,%3},{%4,%5,%6,%7},{%8,%9},{%0,%1,%2,%3};"
        : "+f"(d[0]), "+f"(d[1]), "+f"(d[2]), "+f"(d[3])
        : "r"(a[0]), "r"(a[1]), "r"(a[2]), "r"(a[3]), "r"(b0), "r"(b1));
}
__device__ __forceinline__ void mma_f16(float* d, const u32* a, u32 b0, u32 b1) {
    asm("mma.sync.aligned.m16n8k16.row.col.f32.f16.f16.f32 "
        "{%0,%1,%2,%3},{%4,%5,%6,%7},{%8,%9},{%0,%1,%2,%3};"
        : "+f"(d[0]), "+f"(d[1]), "+f"(d[2]), "+f"(d[3])
        : "r"(a[0]), "r"(a[1]), "r"(a[2]), "r"(a[3]), "r"(b0), "r"(b1));
}
__device__ __forceinline__ void ldsm4(u32* r, u32 addr) {
    asm volatile("ldmatrix.sync.aligned.m8n8.x4.shared.b16 {%0,%1,%2,%3}, [%4];"
                 : "=r"(r[0]), "=r"(r[1]), "=r"(r[2]), "=r"(r[3]) : "r"(addr));
}
__device__ __forceinline__ u32 smem_u32(const void* p) {
    u32 a; asm("{ .reg .u64 t; cvta.to.shared.u64 t, %1; cvt.u32.u64 %0, t; }" : "=r"(a) : "l"(p));
    return a;
}

// ---------------- scratch ----------------
__device__ __nv_bfloat16 g_h1h[(size_t)NSAMP * 16384];  // [n][256 pos][64 ic]
__device__ __nv_bfloat16 g_h1l[(size_t)NSAMP * 16384];
__device__ uint4 g_w1ph[896],  g_w1pl[896];
__device__ uint4 g_w2ph[5120], g_w2pl[5120];
__device__ uint4 g_w3ph[12288], g_w3pl[12288];
__device__ float g_feat[(size_t)NSAMP * 256];
__device__ u16   g_zh[(size_t)NSAMP * 128];
__device__ u16   g_zl[(size_t)NSAMP * 128];
__device__ float g_sq[NSAMP];
__device__ float g_fcwT[256 * 128];

// ---------------- weight prep: fragment-order packing ----------------
__global__ void k_prep_w1(const float* __restrict__ w1) {
    int idx = blockIdx.x * blockDim.x + threadIdx.x;
    if (idx >= 896) return;
    int lane = idx & 31, mt = (idx >> 5) & 3, kt = idx >> 7;
    int g = lane >> 2, tc = lane & 3;
    int m = mt * 16 + g, c = kt * 16 + 2 * tc;
    int rows[4] = {m, m + 8, m, m + 8};
    int cols[4] = {c, c, c + 8, c + 8};
    u32 hq[4], lq[4];
#pragma unroll
    for (int i = 0; i < 4; i++) {
        u16 h0 = 0, l0 = 0, h1 = 0, l1 = 0;
        if (cols[i] < 100)     bsplit(w1[rows[i] * 100 + cols[i]], &h0, &l0);
        if (cols[i] + 1 < 100) bsplit(w1[rows[i] * 100 + cols[i] + 1], &h1, &l1);
        hq[i] = (u32)h0 | ((u32)h1 << 16);
        lq[i] = (u32)l0 | ((u32)l1 << 16);
    }
    g_w1ph[idx] = make_uint4(hq[0], hq[1], hq[2], hq[3]);
    g_w1pl[idx] = make_uint4(lq[0], lq[1], lq[2], lq[3]);
}
__global__ void k_prep_w2(const float* __restrict__ w2) {
    int idx = blockIdx.x * blockDim.x + threadIdx.x;
    if (idx >= 5120) return;
    int lane = idx & 31, mt = (idx >> 5) & 7, kt = (idx >> 8) & 3, s = idx >> 10;
    int g = lane >> 2, tc = lane & 3;
    int m = mt * 16 + g, c = kt * 16 + 2 * tc;
    int rows[4] = {m, m + 8, m, m + 8};
    int cols[4] = {c, c, c + 8, c + 8};
    u32 hq[4], lq[4];
#pragma unroll
    for (int i = 0; i < 4; i++) {
        u16 h0, l0, h1, l1;
        bsplit(w2[rows[i] * 320 + cols[i] * 5 + s], &h0, &l0);
        bsplit(w2[rows[i] * 320 + (cols[i] + 1) * 5 + s], &h1, &l1);
        hq[i] = (u32)h0 | ((u32)h1 << 16);
        lq[i] = (u32)l0 | ((u32)l1 << 16);
    }
    g_w2ph[idx] = make_uint4(hq[0], hq[1], hq[2], hq[3]);
    g_w2pl[idx] = make_uint4(lq[0], lq[1], lq[2], lq[3]);
}
__global__ void k_prep_w3(const float* __restrict__ w3) {
    int idx = blockIdx.x * blockDim.x + threadIdx.x;
    if (idx >= 12288) return;
    int lane = idx & 31, mt = (idx >> 5) & 15, kt = (idx >> 9) & 7, s = idx >> 12;
    int g = lane >> 2, tc = lane & 3;
    int m = mt * 16 + g, c = kt * 16 + 2 * tc;
    int rows[4] = {m, m + 8, m, m + 8};
    int cols[4] = {c, c, c + 8, c + 8};
    u32 hq[4], lq[4];
#pragma unroll
    for (int i = 0; i < 4; i++) {
        u16 h0, l0, h1, l1;
        bsplit(w3[rows[i] * 384 + cols[i] * 3 + s], &h0, &l0);
        bsplit(w3[rows[i] * 384 + (cols[i] + 1) * 3 + s], &h1, &l1);
        hq[i] = (u32)h0 | ((u32)h1 << 16);
        lq[i] = (u32)l0 | ((u32)l1 << 16);
    }
    g_w3ph[idx] = make_uint4(hq[0], hq[1], hq[2], hq[3]);
    g_w3pl[idx] = make_uint4(lq[0], lq[1], lq[2], lq[3]);
}

// ---------------- conv1 (mma.sync, im2col-by-shift) ----------------
#define C1_BL 61440
#define C1_XH 122880
#define C1_XL 123616
#define C1T_SMEM (123616 + 736)
__global__ void __launch_bounds__(512) k_conv1(const float* __restrict__ x,
                                               const float* __restrict__ b1) {
    extern __shared__ __align__(16) char c1sm[];
    u16* Bh = (u16*)c1sm;
    u16* Bl = (u16*)(c1sm + C1_BL);
    u16* xh_s = (u16*)(c1sm + C1_XH);
    u16* xl_s = (u16*)(c1sm + C1_XL);
    const int n = blockIdx.x;
    const int P0 = blockIdx.y * 256;
    const int tid = threadIdx.x;
    const int lane = tid & 31, wp = tid >> 5;
    const float* xn = x + (size_t)n * 512;

    for (int i = tid; i < 355; i += 512) {
        int j = P0 - 49 + i;
        float v = (j >= 0 && j < 512) ? xn[j] : 0.f;
        u16 h, l; bsplit(v, &h, &l);
        xh_s[i] = h; xl_s[i] = l;
    }
    __syncthreads();
    for (int idx = tid; idx < 256 * 60; idx += 512) {
        int row = idx / 60, kp = idx % 60;
        u32 vh = 0, vl = 0;
        if (kp < 50) {
            int base = row + 2 * kp;
            vh = (u32)xh_s[base] | ((u32)xh_s[base + 1] << 16);
            vl = (u32)xl_s[base] | ((u32)xl_s[base + 1] << 16);
        }
        *(u32*)(Bh + row * 120 + 2 * kp) = vh;
        *(u32*)(Bl + row * 120 + 2 * kp) = vl;
    }
    __syncthreads();

    const int mt = wp >> 2, nq = wp & 3;
    const int n0 = nq * 64;
    const int q = lane >> 3, rr = lane & 7;
    const u32 bA = smem_u32(Bh);
    const int rowq = n0 + 8 * (q >> 1) + rr;

    float acc[8][4];
#pragma unroll
    for (int j = 0; j < 8; j++) { acc[j][0] = acc[j][1] = acc[j][2] = acc[j][3] = 0.f; }

#pragma unroll
    for (int kt = 0; kt < 7; kt++) {
        const u32 colb = (u32)(kt * 32 + (q & 1) * 16);
        const uint4 Ah = g_w1ph[(kt * 4 + mt) * 32 + lane];
        const uint4 Al = g_w1pl[(kt * 4 + mt) * 32 + lane];
#pragma unroll
        for (int jp = 0; jp < 4; jp++) {
            u32 ad = bA + (u32)(rowq + jp * 16) * 240u + colb;
            u32 Bh_[4], Bl_[4];
            ldsm4(Bh_, ad);
            ldsm4(Bl_, ad + C1_BL);
            mma_bf16(acc[2 * jp],     (const u32*)&Ah, Bh_[0], Bh_[1]);
            mma_bf16(acc[2 * jp],     (const u32*)&Ah, Bl_[0], Bl_[1]);
            mma_bf16(acc[2 * jp],     (const u32*)&Al, Bh_[0], Bh_[1]);
            mma_bf16(acc[2 * jp + 1], (const u32*)&Ah, Bh_[2], Bh_[3]);
            mma_bf16(acc[2 * jp + 1], (const u32*)&Ah, Bl_[2], Bl_[3]);
            mma_bf16(acc[2 * jp + 1], (const u32*)&Al, Bh_[2], Bh_[3]);
        }
    }
    __syncthreads();

    u16* Sh = (u16*)c1sm;
    u16* Sl = (u16*)(c1sm + 36864);
    const int g2 = lane >> 2, tc = lane & 3;
    const float bi0 = b1[mt * 16 + g2], bi1 = b1[mt * 16 + g2 + 8];
#pragma unroll
    for (int jj = 0; jj < 8; jj++) {
        int pp = nq * 32 + 4 * jj + tc;
        float v0 = fmaxf(fmaxf(acc[jj][0] + bi0, acc[jj][1] + bi0), 0.f);
        float v1 = fmaxf(fmaxf(acc[jj][2] + bi1, acc[jj][3] + bi1), 0.f);
        u16 h, l;
        bsplit(v0, &h, &l);
        Sh[pp * 72 + mt * 16 + g2] = h; Sl[pp * 72 + mt * 16 + g2] = l;
        bsplit(v1, &h, &l);
        Sh[pp * 72 + mt * 16 + g2 + 8] = h; Sl[pp * 72 + mt * 16 + g2 + 8] = l;
    }
    __syncthreads();
    char* dh = (char*)g_h1h + (size_t)n * 32768 + (size_t)blockIdx.y * 16384;
    char* dl = (char*)g_h1l + (size_t)n * 32768 + (size_t)blockIdx.y * 16384;
    for (int i = tid; i < 1024; i += 512) {
        int r = i >> 3, blk = i & 7;
        *(uint4*)(dh + r * 128 + blk * 16) = *(const uint4*)((char*)Sh + r * 144 + blk * 16);
        *(uint4*)(dl + r * 128 + blk * 16) = *(const uint4*)((char*)Sl + r * 144 + blk * 16);
    }
}

// ---------------- fused conv2 -> conv3 (+ pool + mean) ----------------
#define F_X2L (18720 * 2)
#define F_X3OFF 74880
#define F_X3L (17680 * 2)
#define F_SMEM (74880 + 70720)
__global__ void __launch_bounds__(512) k_conv23(const float* __restrict__ b2,
                                                const float* __restrict__ b3) {
    extern __shared__ __align__(16) char fsm[];
    __nv_bfloat16* Xh = (__nv_bfloat16*)fsm;
    u16* X3h = (u16*)(fsm + F_X3OFF);
    u16* X3l = (u16*)(fsm + F_X3OFF + F_X3L);
    const int n = blockIdx.x;
    const int tid = threadIdx.x;
    const int lane = tid & 31, wp = tid >> 5;

    for (int i = tid; i < 128; i += 512) {
        int rr2 = i >> 5;
        int row = (rr2 < 2) ? rr2 : 256 + rr2;
        int cw = i & 31;
        ((u32*)((char*)Xh + row * 144))[cw] = 0u;
        ((u32*)((char*)Xh + F_X2L + row * 144))[cw] = 0u;
    }
    {
        const char* srch = (const char*)g_h1h + (size_t)n * 32768;
        const char* srcl = (const char*)g_h1l + (size_t)n * 32768;
        for (int i = tid; i < 2048; i += 512) {
            int r = i >> 3, blk = i & 7;
            *(uint4*)((char*)Xh + (r + 2) * 144 + blk * 16) = *(const uint4*)(srch + r * 128 + blk * 16);
            *(uint4*)((char*)Xh + F_X2L + (r + 2) * 144 + blk * 16) = *(const uint4*)(srcl + r * 128 + blk * 16);
        }
    }
    for (int i = tid; i < 272; i += 512) {
        int pl = i / 136, rem = i % 136;
        int row = (rem >= 68) ? 129 : 0;
        int w = rem % 68;
        *(u32*)((char*)X3h + pl * F_X3L + row * 272 + w * 4) = 0u;
    }
    __syncthreads();

    const int mp = wp >> 2, nh = (wp >> 1) & 1, jb = wp & 1;
    const int n0 = nh * 128, jbase = jb * 8;
    const int q = lane >> 3, rr = lane & 7;
    const u32 xhA = smem_u32(Xh);
    const int rowq = n0 + 8 * jbase + 8 * (q >> 1) + rr;

    float acc[2][8][4];
#pragma unroll
    for (int m = 0; m < 2; m++)
#pragma unroll
        for (int j = 0; j < 8; j++) { acc[m][j][0] = acc[m][j][1] = acc[m][j][2] = acc[m][j][3] = 0.f; }

    for (int s = 0; s < 5; s++) {
        const u32 rbyte = (u32)(rowq + s) * 144u;
#pragma unroll
        for (int kt = 0; kt < 4; kt++) {
            const u32 colb = (u32)(kt * 32 + (q & 1) * 16);
            const uint4 AhA = g_w2ph[(s * 4 + kt) * 256 + (2 * mp) * 32 + lane];
            const uint4 AlA = g_w2pl[(s * 4 + kt) * 256 + (2 * mp) * 32 + lane];
            const uint4 AhB = g_w2ph[(s * 4 + kt) * 256 + (2 * mp + 1) * 32 + lane];
            const uint4 AlB = g_w2pl[(s * 4 + kt) * 256 + (2 * mp + 1) * 32 + lane];
#pragma unroll
            for (int jp = 0; jp < 4; jp++) {
                u32 ad = xhA + rbyte + (u32)(jp * 2304) + colb;
                u32 Bh_[4], Bl_[4];
                ldsm4(Bh_, ad);
                ldsm4(Bl_, ad + F_X2L);
                mma_bf16(acc[0][2 * jp],     (const u32*)&AhA, Bh_[0], Bh_[1]);
                mma_bf16(acc[0][2 * jp],     (const u32*)&AhA, Bl_[0], Bl_[1]);
                mma_bf16(acc[0][2 * jp],     (const u32*)&AlA, Bh_[0], Bh_[1]);
                mma_bf16(acc[0][2 * jp + 1], (const u32*)&AhA, Bh_[2], Bh_[3]);
                mma_bf16(acc[0][2 * jp + 1], (const u32*)&AhA, Bl_[2], Bl_[3]);
                mma_bf16(acc[0][2 * jp + 1], (const u32*)&AlA, Bh_[2], Bh_[3]);
                mma_bf16(acc[1][2 * jp],     (const u32*)&AhB, Bh_[0], Bh_[1]);
                mma_bf16(acc[1][2 * jp],     (const u32*)&AhB, Bl_[0], Bl_[1]);
                mma_bf16(acc[1][2 * jp],     (const u32*)&AlB, Bh_[0], Bh_[1]);
                mma_bf16(acc[1][2 * jp + 1], (const u32*)&AhB, Bh_[2], Bh_[3]);
                mma_bf16(acc[1][2 * jp + 1], (const u32*)&AhB, Bl_[2], Bl_[3]);
                mma_bf16(acc[1][2 * jp + 1], (const u32*)&AlB, Bh_[2], Bh_[3]);
            }
        }
    }

    const int g2 = lane >> 2, tc = lane & 3;
#pragma unroll
    for (int m = 0; m < 2; m++) {
        const int m0 = mp * 32 + m * 16;
        const float bi0 = b2[m0 + g2], bi1 = b2[m0 + g2 + 8];
#pragma unroll
        for (int jl = 0; jl < 8; jl++) {
            int pp = n0 / 2 + 4 * (jbase + jl) + tc;
            float v0 = fmaxf(fmaxf(acc[m][jl][0] + bi0, acc[m][jl][1] + bi0), 0.f);
            float v1 = fmaxf(fmaxf(acc[m][jl][2] + bi1, acc[m][jl][3] + bi1), 0.f);
            u16 h, l;
            bsplit(v0, &h, &l);
            X3h[(pp + 1) * 136 + m0 + g2] = h; X3l[(pp + 1) * 136 + m0 + g2] = l;
            bsplit(v1, &h, &l);
            X3h[(pp + 1) * 136 + m0 + g2 + 8] = h; X3l[(pp + 1) * 136 + m0 + g2 + 8] = l;
        }
    }
    __syncthreads();

    const int mp3 = wp >> 1, jb3 = wp & 1;
    const int jbase3 = jb3 * 8;
    const u32 x3A = smem_u32(X3h);
    const int rowq3 = 8 * jbase3 + 8 * (q >> 1) + rr;

#pragma unroll
    for (int m = 0; m < 2; m++)
#pragma unroll
        for (int j = 0; j < 8; j++) { acc[m][j][0] = acc[m][j][1] = acc[m][j][2] = acc[m][j][3] = 0.f; }

    for (int s = 0; s < 3; s++) {
        const u32 rbyte = (u32)(rowq3 + s) * 272u;
#pragma unroll
        for (int kt = 0; kt < 8; kt++) {
            const u32 colb = (u32)(kt * 32 + (q & 1) * 16);
            const uint4 AhA = g_w3ph[(s * 8 + kt) * 512 + (2 * mp3) * 32 + lane];
            const uint4 AlA = g_w3pl[(s * 8 + kt) * 512 + (2 * mp3) * 32 + lane];
            const uint4 AhB = g_w3ph[(s * 8 + kt) * 512 + (2 * mp3 + 1) * 32 + lane];
            const uint4 AlB = g_w3pl[(s * 8 + kt) * 512 + (2 * mp3 + 1) * 32 + lane];
#pragma unroll
            for (int jp = 0; jp < 4; jp++) {
                u32 ad = x3A + rbyte + (u32)(jp * 4352) + colb;
                u32 Bh_[4], Bl_[4];
                ldsm4(Bh_, ad);
                ldsm4(Bl_, ad + F_X3L);
                mma_bf16(acc[0][2 * jp],     (const u32*)&AhA, Bh_[0], Bh_[1]);
                mma_bf16(acc[0][2 * jp],     (const u32*)&AhA, Bl_[0], Bl_[1]);
                mma_bf16(acc[0][2 * jp],     (const u32*)&AlA, Bh_[0], Bh_[1]);
                mma_bf16(acc[0][2 * jp + 1], (const u32*)&AhA, Bh_[2], Bh_[3]);
                mma_bf16(acc[0][2 * jp + 1], (const u32*)&AhA, Bl_[2], Bl_[3]);
                mma_bf16(acc[0][2 * jp + 1], (const u32*)&AlA, Bh_[2], Bh_[3]);
                mma_bf16(acc[1][2 * jp],     (const u32*)&AhB, Bh_[0], Bh_[1]);
                mma_bf16(acc[1][2 * jp],     (const u32*)&AhB, Bl_[0], Bl_[1]);
                mma_bf16(acc[1][2 * jp],     (const u32*)&AlB, Bh_[0], Bh_[1]);
                mma_bf16(acc[1][2 * jp + 1], (const u32*)&AhB, Bh_[2], Bh_[3]);
                mma_bf16(acc[1][2 * jp + 1], (const u32*)&AhB, Bl_[2], Bl_[3]);
                mma_bf16(acc[1][2 * jp + 1], (const u32*)&AlB, Bh_[2], Bh_[3]);
            }
        }
    }
    __syncthreads();

    float* part = (float*)fsm;
#pragma unroll
    for (int m = 0; m < 2; m++) {
        const int m0 = mp3 * 32 + m * 16;
        const float bi0 = b3[m0 + g2], bi1 = b3[m0 + g2 + 8];
        float s0 = 0.f, s1 = 0.f;
#pragma unroll
        for (int jl = 0; jl < 8; jl++) {
            float a0 = fmaxf(acc[m][jl][0] + bi0, 0.f);
            float a1 = fmaxf(acc[m][jl][1] + bi0, 0.f);
            s0 += fmaxf(a0, a1);
            float c0 = fmaxf(acc[m][jl][2] + bi1, 0.f);
            float c1 = fmaxf(acc[m][jl][3] + bi1, 0.f);
            s1 += fmaxf(c0, c1);
        }
        s0 += __shfl_xor_sync(0xFFFFFFFFu, s0, 1);
        s0 += __shfl_xor_sync(0xFFFFFFFFu, s0, 2);
        s1 += __shfl_xor_sync(0xFFFFFFFFu, s1, 1);
        s1 += __shfl_xor_sync(0xFFFFFFFFu, s1, 2);
        if (tc == 0) {
            part[(m0 + g2) * 2 + jb3]     = s0;
            part[(m0 + g2 + 8) * 2 + jb3] = s1;
        }
    }
    __syncthreads();
    if (tid < 256) {
        g_feat[(size_t)n * 256 + tid] = (part[2 * tid] + part[2 * tid + 1]) * (1.f / 64.f);
    }
}

// ---------------- fc weight transpose ----------------
__global__ void k_fcT(const float* __restrict__ fcw) {
    int idx = blockIdx.x * blockDim.x + threadIdx.x;
    if (idx < 128 * 256) {
        int j = idx / 256, k = idx % 256;
        g_fcwT[k * 128 + j] = fcw[idx];
    }
}

// ---------------- fc + relu + bn (z -> fp16 split) ----------------
__global__ void k_fc(const float* __restrict__ fcb, const float* __restrict__ gamma,
                     const float* __restrict__ beta, const float* __restrict__ mean,
                     const float* __restrict__ var) {
    const int n = blockIdx.x;
    const int j = threadIdx.x;
    __shared__ float fs[256];
    __shared__ float ps[4];
    fs[j]       = g_feat[(size_t)n * 256 + j];
    fs[j + 128] = g_feat[(size_t)n * 256 + 128 + j];
    __syncthreads();
    float acc = fcb[j];
#pragma unroll 8
    for (int k = 0; k < 256; k++) acc = fmaf(fs[k], g_fcwT[k * 128 + j], acc);
    acc = fmaxf(acc, 0.f);
    float z = gamma[j] * (acc - mean[j]) * rsqrtf(var[j] + 1e-5f) + beta[j];
    u16 zh, zl; hsplit(z, &zh, &zl);
    g_zh[(size_t)n * 128 + j] = zh;
    g_zl[(size_t)n * 128 + j] = zl;
    float s = z * z;
#pragma unroll
    for (int off = 16; off; off >>= 1) s += __shfl_xor_sync(0xFFFFFFFFu, s, off);
    if ((j & 31) == 0) ps[j >> 5] = s;
    __syncthreads();
    if (j == 0) g_sq[n] = ps[0] + ps[1] + ps[2] + ps[3];
}

// ---------------- pairwise (mma.sync fp16 split, 256x128 tile, 512 threads) ----------------
#define PA_L 69632               // A plane stride (256*272)
#define PB_L 34816               // B plane stride (128*272)
#define PB_OFF 139264            // B base (after 2 A planes)
#define PT_SMEM (139264 + 69632) // 208,896 B
__global__ void __launch_bounds__(512) k_pair(const int* __restrict__ info, float* __restrict__ out) {
    extern __shared__ __align__(16) char psm[];
    u16* Ash = (u16*)psm;
    u16* Bsh = (u16*)(psm + PB_OFF);
    const int ib = blockIdx.y * 256;
    const int jbb = blockIdx.x * 128;
    const int tid = threadIdx.x;  // 512
    const int lane = tid & 31, wp = tid >> 5;

    for (int i = tid; i < 4096; i += 512) {   // A: 256 rows x 16 uint4
        int r = i >> 4, c = i & 15;
        *(uint4*)((char*)Ash + r * 272 + c * 16)        = ((const uint4*)(g_zh + (size_t)(ib + r) * 128))[c];
        *(uint4*)((char*)Ash + PA_L + r * 272 + c * 16) = ((const uint4*)(g_zl + (size_t)(ib + r) * 128))[c];
    }
    for (int i = tid; i < 2048; i += 512) {   // B: 128 rows x 16 uint4
        int r = i >> 4, c = i & 15;
        *(uint4*)((char*)Bsh + r * 272 + c * 16)        = ((const uint4*)(g_zh + (size_t)(jbb + r) * 128))[c];
        *(uint4*)((char*)Bsh + PB_L + r * 272 + c * 16) = ((const uint4*)(g_zl + (size_t)(jbb + r) * 128))[c];
    }
    __syncthreads();

    const int mh = wp >> 1, nh = wp & 1;        // 8 m-slices x 2 n-halves
    const int m0base = 32 * mh, jbase = nh * 8;
    const u32 aA = smem_u32(Ash);
    const u32 bB = smem_u32(Bsh);
    const int jA = lane >> 3, rA = lane & 7;
    const int arow = (jA & 1) * 8 + rA;
    const u32 acol = (u32)((jA >> 1) * 16);
    const int q = lane >> 3, rr = lane & 7;
    const int browq = jbase * 8 + 8 * (q >> 1) + rr;
    const u32 bcol = (u32)((q & 1) * 16);

    float acc[2][8][4];
#pragma unroll
    for (int m = 0; m < 2; m++)
#pragma unroll
        for (int j = 0; j < 8; j++) { acc[m][j][0] = acc[m][j][1] = acc[m][j][2] = acc[m][j][3] = 0.f; }

#pragma unroll
    for (int kt = 0; kt < 8; kt++) {
        u32 Ah_[2][4], Al_[2][4];
#pragma unroll
        for (int mi = 0; mi < 2; mi++) {
            u32 aad = aA + (u32)(m0base + mi * 16 + arow) * 272u + (u32)(kt * 32) + acol;
            ldsm4(Ah_[mi], aad);
            ldsm4(Al_[mi], aad + PA_L);
        }
#pragma unroll
        for (int jp = 0; jp < 4; jp++) {
            u32 bad = bB + (u32)(browq + jp * 16) * 272u + (u32)(kt * 32) + bcol;
            u32 Bh_[4], Bl_[4];
            ldsm4(Bh_, bad);
            ldsm4(Bl_, bad + PB_L);
#pragma unroll
            for (int mi = 0; mi < 2; mi++) {
                mma_f16(acc[mi][2 * jp],     Ah_[mi], Bh_[0], Bh_[1]);
                mma_f16(acc[mi][2 * jp],     Ah_[mi], Bl_[0], Bl_[1]);
                mma_f16(acc[mi][2 * jp],     Al_[mi], Bh_[0], Bh_[1]);
                mma_f16(acc[mi][2 * jp + 1], Ah_[mi], Bh_[2], Bh_[3]);
                mma_f16(acc[mi][2 * jp + 1], Ah_[mi], Bl_[2], Bl_[3]);
                mma_f16(acc[mi][2 * jp + 1], Al_[mi], Bh_[2], Bh_[3]);
            }
        }
    }

    const int g2 = lane >> 2, tc = lane & 3;
#pragma unroll
    for (int mi = 0; mi < 2; mi++) {
#pragma unroll
        for (int rh = 0; rh < 2; rh++) {
            const int i = ib + m0base + mi * 16 + g2 + rh * 8;
            const float sqi = g_sq[i];
            const int wti = info[2 * i], gi = info[2 * i + 1];
#pragma unroll
            for (int jl = 0; jl < 8; jl++) {
                const int j0 = jbb + nh * 64 + 8 * jl + 2 * tc;
                float c0 = acc[mi][jl][2 * rh], c1 = acc[mi][jl][2 * rh + 1];
                float2 res;
                {
                    float d2 = sqi + g_sq[j0] - 2.f * c0;
                    float d = sqrtf(fmaxf(d2, 0.f));
                    bool y = (wti == info[2 * j0]) && (gi == 1) && (info[2 * j0 + 1] == 1);
                    float cl = y ? d : fmaxf(1.f - d, 0.f);
                    res.x = (i == j0) ? 0.f : cl;
                }
                {
                    int j1 = j0 + 1;
                    float d2 = sqi + g_sq[j1] - 2.f * c1;
                    float d = sqrtf(fmaxf(d2, 0.f));
                    bool y = (wti == info[2 * j1]) && (gi == 1) && (info[2 * j1 + 1] == 1);
                    float cl = y ? d : fmaxf(1.f - d, 0.f);
                    res.y = (i == j1) ? 0.f : cl;
                }
                *reinterpret_cast<float2*>(out + (size_t)i * 4096 + j0) = res;
            }
        }
    }
}

// ---------------- launch ----------------
extern "C" void kernel_launch(void* const* d_in, const int* in_sizes, int n_in,
                              void* d_out, int out_size) {
    const float* samples = (const float*)d_in[0];
    const int*   info    = (const int*)d_in[1];
    const float* w1  = (const float*)d_in[2];
    const float* b1  = (const float*)d_in[3];
    const float* w2  = (const float*)d_in[4];
    const float* b2  = (const float*)d_in[5];
    const float* w3  = (const float*)d_in[6];
    const float* b3  = (const float*)d_in[7];
    const float* fcw = (const float*)d_in[8];
    const float* fcb = (const float*)d_in[9];
    const float* gam = (const float*)d_in[10];
    const float* bet = (const float*)d_in[11];
    const float* bmu = (const float*)d_in[12];
    const float* bva = (const float*)d_in[13];
    float* out = (float*)d_out;

    cudaFuncSetAttribute(k_conv1, cudaFuncAttributeMaxDynamicSharedMemorySize, C1T_SMEM);
    cudaFuncSetAttribute(k_conv23, cudaFuncAttributeMaxDynamicSharedMemorySize, F_SMEM);
    cudaFuncSetAttribute(k_pair,  cudaFuncAttributeMaxDynamicSharedMemorySize, PT_SMEM);

    k_prep_w1<<<4, 256>>>(w1);
    k_prep_w2<<<20, 256>>>(w2);
    k_prep_w3<<<48, 256>>>(w3);
    k_fcT<<<64, 512>>>(fcw);
    k_conv1<<<dim3(NSAMP, 2), 512, C1T_SMEM>>>(samples, b1);
    k_conv23<<<NSAMP, 512, F_SMEM>>>(b2, b3);
    k_fc<<<NSAMP, 128>>>(fcb, gam, bet, bmu, bva);
    k_pair<<<dim3(32, 16), 512, PT_SMEM>>>(info, out);
}

// round 17
// speedup vs baseline: 1.4480x; 1.0055x over previous
#include <cuda_runtime.h>
#include <cuda_bf16.h>
#include <cuda_fp16.h>
#include <cstdint>

#define NSAMP 4096
typedef unsigned long long u64;
typedef unsigned int u32;
typedef unsigned short u16;

// ---------------- split + mma + ldmatrix helpers ----------------
__device__ __forceinline__ void bsplit(float x, u16* h, u16* l) {
    __nv_bfloat16 hh = __float2bfloat16_rn(x);
    *h = __bfloat16_as_ushort(hh);
    *l = __bfloat16_as_ushort(__float2bfloat16_rn(x - __bfloat162float(hh)));
}
__device__ __forceinline__ void hsplit(float x, u16* h, u16* l) {
    __half hh = __float2half_rn(x);
    *h = __half_as_ushort(hh);
    *l = __half_as_ushort(__float2half_rn(x - __half2float(hh)));
}
__device__ __forceinline__ void mma_bf16(float* d, const u32* a, u32 b0, u32 b1) {
    asm("mma.sync.aligned.m16n8k16.row.col.f32.bf16.bf16.f32 "
        "{%0,%1,%2,%3},{%4,%5,%6,%7},{%8,%9},{%0,%1,%2,%3};"
        : "+f"(d[0]), "+f"(d[1]), "+f"(d[2]), "+f"(d[3])
        : "r"(a[0]), "r"(a[1]), "r"(a[2]), "r"(a[3]), "r"(b0), "r"(b1));
}
__device__ __forceinline__ void mma_f16(float* d, const u32* a, u32 b0, u32 b1) {
    asm("mma.sync.aligned.m16n8k16.row.col.f32.f16.f16.f32 "
        "{%0,%1,%2,%3},{%4,%5,%6,%7},{%8,%9},{%0,%1,%2,%3};"
        : "+f"(d[0]), "+f"(d[1]), "+f"(d[2]), "+f"(d[3])
        : "r"(a[0]), "r"(a[1]), "r"(a[2]), "r"(a[3]), "r"(b0), "r"(b1));
}
__device__ __forceinline__ void ldsm4(u32* r, u32 addr) {
    asm volatile("ldmatrix.sync.aligned.m8n8.x4.shared.b16 {%0,%1,%2,%3}, [%4];"
                 : "=r"(r[0]), "=r"(r[1]), "=r"(r[2]), "=r"(r[3]) : "r"(addr));
}
__device__ __forceinline__ u32 smem_u32(const void* p) {
    u32 a; asm("{ .reg .u64 t; cvta.to.shared.u64 t, %1; cvt.u32.u64 %0, t; }" : "=r"(a) : "l"(p));
    return a;
}
__device__ __forceinline__ void cpasync16(u32 dst, const void* src) {
    asm volatile("cp.async.cg.shared.global [%0], [%1], 16;" :: "r"(dst), "l"(src));
}
#define CP_COMMIT() asm volatile("cp.async.commit_group;" ::: "memory")
#define CP_WAIT0()  asm volatile("cp.async.wait_group 0;" ::: "memory")

// ---------------- scratch ----------------
__device__ __nv_bfloat16 g_h1h[(size_t)NSAMP * 16384];  // [n][256 pos][64 ic]
__device__ __nv_bfloat16 g_h1l[(size_t)NSAMP * 16384];
__device__ uint4 g_w1ph[896],  g_w1pl[896];
__device__ uint4 g_w2ph[5120], g_w2pl[5120];
__device__ uint4 g_w3ph[12288], g_w3pl[12288];
__device__ float g_feat[(size_t)NSAMP * 256];
__device__ u16   g_zh[(size_t)NSAMP * 128];
__device__ u16   g_zl[(size_t)NSAMP * 128];
__device__ float g_sq[NSAMP];
__device__ float g_fcwT[256 * 128];

// ---------------- weight prep: fragment-order packing ----------------
__global__ void k_prep_w1(const float* __restrict__ w1) {
    int idx = blockIdx.x * blockDim.x + threadIdx.x;
    if (idx >= 896) return;
    int lane = idx & 31, mt = (idx >> 5) & 3, kt = idx >> 7;
    int g = lane >> 2, tc = lane & 3;
    int m = mt * 16 + g, c = kt * 16 + 2 * tc;
    int rows[4] = {m, m + 8, m, m + 8};
    int cols[4] = {c, c, c + 8, c + 8};
    u32 hq[4], lq[4];
#pragma unroll
    for (int i = 0; i < 4; i++) {
        u16 h0 = 0, l0 = 0, h1 = 0, l1 = 0;
        if (cols[i] < 100)     bsplit(w1[rows[i] * 100 + cols[i]], &h0, &l0);
        if (cols[i] + 1 < 100) bsplit(w1[rows[i] * 100 + cols[i] + 1], &h1, &l1);
        hq[i] = (u32)h0 | ((u32)h1 << 16);
        lq[i] = (u32)l0 | ((u32)l1 << 16);
    }
    g_w1ph[idx] = make_uint4(hq[0], hq[1], hq[2], hq[3]);
    g_w1pl[idx] = make_uint4(lq[0], lq[1], lq[2], lq[3]);
}
__global__ void k_prep_w2(const float* __restrict__ w2) {
    int idx = blockIdx.x * blockDim.x + threadIdx.x;
    if (idx >= 5120) return;
    int lane = idx & 31, mt = (idx >> 5) & 7, kt = (idx >> 8) & 3, s = idx >> 10;
    int g = lane >> 2, tc = lane & 3;
    int m = mt * 16 + g, c = kt * 16 + 2 * tc;
    int rows[4] = {m, m + 8, m, m + 8};
    int cols[4] = {c, c, c + 8, c + 8};
    u32 hq[4], lq[4];
#pragma unroll
    for (int i = 0; i < 4; i++) {
        u16 h0, l0, h1, l1;
        bsplit(w2[rows[i] * 320 + cols[i] * 5 + s], &h0, &l0);
        bsplit(w2[rows[i] * 320 + (cols[i] + 1) * 5 + s], &h1, &l1);
        hq[i] = (u32)h0 | ((u32)h1 << 16);
        lq[i] = (u32)l0 | ((u32)l1 << 16);
    }
    g_w2ph[idx] = make_uint4(hq[0], hq[1], hq[2], hq[3]);
    g_w2pl[idx] = make_uint4(lq[0], lq[1], lq[2], lq[3]);
}
__global__ void k_prep_w3(const float* __restrict__ w3) {
    int idx = blockIdx.x * blockDim.x + threadIdx.x;
    if (idx >= 12288) return;
    int lane = idx & 31, mt = (idx >> 5) & 15, kt = (idx >> 9) & 7, s = idx >> 12;
    int g = lane >> 2, tc = lane & 3;
    int m = mt * 16 + g, c = kt * 16 + 2 * tc;
    int rows[4] = {m, m + 8, m, m + 8};
    int cols[4] = {c, c, c + 8, c + 8};
    u32 hq[4], lq[4];
#pragma unroll
    for (int i = 0; i < 4; i++) {
        u16 h0, l0, h1, l1;
        bsplit(w3[rows[i] * 384 + cols[i] * 3 + s], &h0, &l0);
        bsplit(w3[rows[i] * 384 + (cols[i] + 1) * 3 + s], &h1, &l1);
        hq[i] = (u32)h0 | ((u32)h1 << 16);
        lq[i] = (u32)l0 | ((u32)l1 << 16);
    }
    g_w3ph[idx] = make_uint4(hq[0], hq[1], hq[2], hq[3]);
    g_w3pl[idx] = make_uint4(lq[0], lq[1], lq[2], lq[3]);
}

// ---------------- conv1 (mma.sync, im2col-by-shift) ----------------
#define C1_BL 61440
#define C1_XH 122880
#define C1_XL 123616
#define C1T_SMEM (123616 + 736)
__global__ void __launch_bounds__(512) k_conv1(const float* __restrict__ x,
                                               const float* __restrict__ b1) {
    extern __shared__ __align__(16) char c1sm[];
    u16* Bh = (u16*)c1sm;
    u16* Bl = (u16*)(c1sm + C1_BL);
    u16* xh_s = (u16*)(c1sm + C1_XH);
    u16* xl_s = (u16*)(c1sm + C1_XL);
    const int n = blockIdx.x;
    const int P0 = blockIdx.y * 256;
    const int tid = threadIdx.x;
    const int lane = tid & 31, wp = tid >> 5;
    const float* xn = x + (size_t)n * 512;

    for (int i = tid; i < 355; i += 512) {
        int j = P0 - 49 + i;
        float v = (j >= 0 && j < 512) ? xn[j] : 0.f;
        u16 h, l; bsplit(v, &h, &l);
        xh_s[i] = h; xl_s[i] = l;
    }
    __syncthreads();
    for (int idx = tid; idx < 256 * 60; idx += 512) {
        int row = idx / 60, kp = idx % 60;
        u32 vh = 0, vl = 0;
        if (kp < 50) {
            int base = row + 2 * kp;
            vh = (u32)xh_s[base] | ((u32)xh_s[base + 1] << 16);
            vl = (u32)xl_s[base] | ((u32)xl_s[base + 1] << 16);
        }
        *(u32*)(Bh + row * 120 + 2 * kp) = vh;
        *(u32*)(Bl + row * 120 + 2 * kp) = vl;
    }
    __syncthreads();

    const int mt = wp >> 2, nq = wp & 3;
    const int n0 = nq * 64;
    const int q = lane >> 3, rr = lane & 7;
    const u32 bA = smem_u32(Bh);
    const int rowq = n0 + 8 * (q >> 1) + rr;

    float acc[8][4];
#pragma unroll
    for (int j = 0; j < 8; j++) { acc[j][0] = acc[j][1] = acc[j][2] = acc[j][3] = 0.f; }

#pragma unroll
    for (int kt = 0; kt < 7; kt++) {
        const u32 colb = (u32)(kt * 32 + (q & 1) * 16);
        const uint4 Ah = g_w1ph[(kt * 4 + mt) * 32 + lane];
        const uint4 Al = g_w1pl[(kt * 4 + mt) * 32 + lane];
#pragma unroll
        for (int jp = 0; jp < 4; jp++) {
            u32 ad = bA + (u32)(rowq + jp * 16) * 240u + colb;
            u32 Bh_[4], Bl_[4];
            ldsm4(Bh_, ad);
            ldsm4(Bl_, ad + C1_BL);
            mma_bf16(acc[2 * jp],     (const u32*)&Ah, Bh_[0], Bh_[1]);
            mma_bf16(acc[2 * jp],     (const u32*)&Ah, Bl_[0], Bl_[1]);
            mma_bf16(acc[2 * jp],     (const u32*)&Al, Bh_[0], Bh_[1]);
            mma_bf16(acc[2 * jp + 1], (const u32*)&Ah, Bh_[2], Bh_[3]);
            mma_bf16(acc[2 * jp + 1], (const u32*)&Ah, Bl_[2], Bl_[3]);
            mma_bf16(acc[2 * jp + 1], (const u32*)&Al, Bh_[2], Bh_[3]);
        }
    }
    __syncthreads();

    u16* Sh = (u16*)c1sm;
    u16* Sl = (u16*)(c1sm + 36864);
    const int g2 = lane >> 2, tc = lane & 3;
    const float bi0 = b1[mt * 16 + g2], bi1 = b1[mt * 16 + g2 + 8];
#pragma unroll
    for (int jj = 0; jj < 8; jj++) {
        int pp = nq * 32 + 4 * jj + tc;
        float v0 = fmaxf(fmaxf(acc[jj][0] + bi0, acc[jj][1] + bi0), 0.f);
        float v1 = fmaxf(fmaxf(acc[jj][2] + bi1, acc[jj][3] + bi1), 0.f);
        u16 h, l;
        bsplit(v0, &h, &l);
        Sh[pp * 72 + mt * 16 + g2] = h; Sl[pp * 72 + mt * 16 + g2] = l;
        bsplit(v1, &h, &l);
        Sh[pp * 72 + mt * 16 + g2 + 8] = h; Sl[pp * 72 + mt * 16 + g2 + 8] = l;
    }
    __syncthreads();
    char* dh = (char*)g_h1h + (size_t)n * 32768 + (size_t)blockIdx.y * 16384;
    char* dl = (char*)g_h1l + (size_t)n * 32768 + (size_t)blockIdx.y * 16384;
    for (int i = tid; i < 1024; i += 512) {
        int r = i >> 3, blk = i & 7;
        *(uint4*)(dh + r * 128 + blk * 16) = *(const uint4*)((char*)Sh + r * 144 + blk * 16);
        *(uint4*)(dl + r * 128 + blk * 16) = *(const uint4*)((char*)Sl + r * 144 + blk * 16);
    }
}

// ---------------- persistent fused conv2 -> conv3 (+ pool + mean) ----------------
#define P_X2BUF 74880
#define P_X2L 37440
#define P_X3OFF 149760
#define P_X3L 35360
#define P_PART 220480
#define P_SMEM (220480 + 2048)
#define NPERS 148
__global__ void __launch_bounds__(512) k_conv23(const float* __restrict__ b2,
                                                const float* __restrict__ b3) {
    extern __shared__ __align__(16) char fsm[];
    u16* X3h = (u16*)(fsm + P_X3OFF);
    u16* X3l = (u16*)(fsm + P_X3OFF + P_X3L);
    float* part = (float*)(fsm + P_PART);
    const int tid = threadIdx.x;
    const int lane = tid & 31, wp = tid >> 5;
    const int q = lane >> 3, rr = lane & 7;
    const int g2 = lane >> 2, tc = lane & 3;
    const u32 sb = smem_u32(fsm);

    for (int i = tid; i < 576; i += 512) {
        int buf = i / 288, rem1 = i % 288;
        int pl = rem1 / 144, rem = rem1 % 144;
        int rr2 = rem / 36;
        int row = (rr2 < 2) ? rr2 : 256 + rr2;
        int cw = rem % 36;
        *(u32*)(fsm + buf * P_X2BUF + pl * P_X2L + row * 144 + cw * 4) = 0u;
    }
    for (int i = tid; i < 272; i += 512) {
        int pl = i / 136, rem = i % 136;
        int row = (rem >= 68) ? 129 : 0;
        int w = rem % 68;
        *(u32*)((char*)X3h + pl * P_X3L + row * 272 + w * 4) = 0u;
    }

    {
        int n0s = blockIdx.x;
        const char* srch = (const char*)g_h1h + (size_t)n0s * 32768;
        const char* srcl = (const char*)g_h1l + (size_t)n0s * 32768;
        for (int i = tid; i < 2048; i += 512) {
            int r = i >> 3, blk = i & 7;
            u32 d = sb + (u32)((r + 2) * 144 + blk * 16);
            cpasync16(d, srch + r * 128 + blk * 16);
            cpasync16(d + P_X2L, srcl + r * 128 + blk * 16);
        }
    }
    CP_COMMIT();

    int iter = 0;
    for (int n = blockIdx.x; n < NSAMP; n += NPERS, iter++) {
        const int buf = iter & 1;
        const u32 x2base = sb + (u32)(buf * P_X2BUF);

        CP_WAIT0();
        __syncthreads();

        if (n + NPERS < NSAMP) {
            const char* srch = (const char*)g_h1h + (size_t)(n + NPERS) * 32768;
            const char* srcl = (const char*)g_h1l + (size_t)(n + NPERS) * 32768;
            const u32 obase = sb + (u32)((buf ^ 1) * P_X2BUF);
            for (int i = tid; i < 2048; i += 512) {
                int r = i >> 3, blk = i & 7;
                u32 d = obase + (u32)((r + 2) * 144 + blk * 16);
                cpasync16(d, srch + r * 128 + blk * 16);
                cpasync16(d + P_X2L, srcl + r * 128 + blk * 16);
            }
        }
        CP_COMMIT();

        // ================= conv2 =================
        const int mp = wp >> 2, nh = (wp >> 1) & 1, jb = wp & 1;
        const int n0 = nh * 128, jbase = jb * 8;
        const int rowq = n0 + 8 * jbase + 8 * (q >> 1) + rr;

        float acc[2][8][4];
#pragma unroll
        for (int m = 0; m < 2; m++)
#pragma unroll
            for (int j = 0; j < 8; j++) { acc[m][j][0] = acc[m][j][1] = acc[m][j][2] = acc[m][j][3] = 0.f; }

        for (int s = 0; s < 5; s++) {
            const u32 rbyte = (u32)(rowq + s) * 144u;
#pragma unroll
            for (int kt = 0; kt < 4; kt++) {
                const u32 colb = (u32)(kt * 32 + (q & 1) * 16);
                const uint4 AhA = g_w2ph[(s * 4 + kt) * 256 + (2 * mp) * 32 + lane];
                const uint4 AlA = g_w2pl[(s * 4 + kt) * 256 + (2 * mp) * 32 + lane];
                const uint4 AhB = g_w2ph[(s * 4 + kt) * 256 + (2 * mp + 1) * 32 + lane];
                const uint4 AlB = g_w2pl[(s * 4 + kt) * 256 + (2 * mp + 1) * 32 + lane];
#pragma unroll
                for (int jp = 0; jp < 4; jp++) {
                    u32 ad = x2base + rbyte + (u32)(jp * 2304) + colb;
                    u32 Bh_[4], Bl_[4];
                    ldsm4(Bh_, ad);
                    ldsm4(Bl_, ad + P_X2L);
                    mma_bf16(acc[0][2 * jp],     (const u32*)&AhA, Bh_[0], Bh_[1]);
                    mma_bf16(acc[0][2 * jp],     (const u32*)&AhA, Bl_[0], Bl_[1]);
                    mma_bf16(acc[0][2 * jp],     (const u32*)&AlA, Bh_[0], Bh_[1]);
                    mma_bf16(acc[0][2 * jp + 1], (const u32*)&AhA, Bh_[2], Bh_[3]);
                    mma_bf16(acc[0][2 * jp + 1], (const u32*)&AhA, Bl_[2], Bl_[3]);
                    mma_bf16(acc[0][2 * jp + 1], (const u32*)&AlA, Bh_[2], Bh_[3]);
                    mma_bf16(acc[1][2 * jp],     (const u32*)&AhB, Bh_[0], Bh_[1]);
                    mma_bf16(acc[1][2 * jp],     (const u32*)&AhB, Bl_[0], Bl_[1]);
                    mma_bf16(acc[1][2 * jp],     (const u32*)&AlB, Bh_[0], Bh_[1]);
                    mma_bf16(acc[1][2 * jp + 1], (const u32*)&AhB, Bh_[2], Bh_[3]);
                    mma_bf16(acc[1][2 * jp + 1], (const u32*)&AhB, Bl_[2], Bl_[3]);
                    mma_bf16(acc[1][2 * jp + 1], (const u32*)&AlB, Bh_[2], Bh_[3]);
                }
            }
        }

#pragma unroll
        for (int m = 0; m < 2; m++) {
            const int m0 = mp * 32 + m * 16;
            const float bi0 = b2[m0 + g2], bi1 = b2[m0 + g2 + 8];
#pragma unroll
            for (int jl = 0; jl < 8; jl++) {
                int pp = n0 / 2 + 4 * (jbase + jl) + tc;
                float v0 = fmaxf(fmaxf(acc[m][jl][0] + bi0, acc[m][jl][1] + bi0), 0.f);
                float v1 = fmaxf(fmaxf(acc[m][jl][2] + bi1, acc[m][jl][3] + bi1), 0.f);
                u16 h, l;
                bsplit(v0, &h, &l);
                X3h[(pp + 1) * 136 + m0 + g2] = h; X3l[(pp + 1) * 136 + m0 + g2] = l;
                bsplit(v1, &h, &l);
                X3h[(pp + 1) * 136 + m0 + g2 + 8] = h; X3l[(pp + 1) * 136 + m0 + g2 + 8] = l;
            }
        }
        __syncthreads();

        // ================= conv3 =================
        const int mp3 = wp >> 1, jb3 = wp & 1;
        const int jbase3 = jb3 * 8;
        const u32 x3A = smem_u32(X3h);
        const int rowq3 = 8 * jbase3 + 8 * (q >> 1) + rr;

#pragma unroll
        for (int m = 0; m < 2; m++)
#pragma unroll
            for (int j = 0; j < 8; j++) { acc[m][j][0] = acc[m][j][1] = acc[m][j][2] = acc[m][j][3] = 0.f; }

        for (int s = 0; s < 3; s++) {
            const u32 rbyte = (u32)(rowq3 + s) * 272u;
#pragma unroll
            for (int kt = 0; kt < 8; kt++) {
                const u32 colb = (u32)(kt * 32 + (q & 1) * 16);
                const uint4 AhA = g_w3ph[(s * 8 + kt) * 512 + (2 * mp3) * 32 + lane];
                const uint4 AlA = g_w3pl[(s * 8 + kt) * 512 + (2 * mp3) * 32 + lane];
                const uint4 AhB = g_w3ph[(s * 8 + kt) * 512 + (2 * mp3 + 1) * 32 + lane];
                const uint4 AlB = g_w3pl[(s * 8 + kt) * 512 + (2 * mp3 + 1) * 32 + lane];
#pragma unroll
                for (int jp = 0; jp < 4; jp++) {
                    u32 ad = x3A + rbyte + (u32)(jp * 4352) + colb;
                    u32 Bh_[4], Bl_[4];
                    ldsm4(Bh_, ad);
                    ldsm4(Bl_, ad + P_X3L);
                    mma_bf16(acc[0][2 * jp],     (const u32*)&AhA, Bh_[0], Bh_[1]);
                    mma_bf16(acc[0][2 * jp],     (const u32*)&AhA, Bl_[0], Bl_[1]);
                    mma_bf16(acc[0][2 * jp],     (const u32*)&AlA, Bh_[0], Bh_[1]);
                    mma_bf16(acc[0][2 * jp + 1], (const u32*)&AhA, Bh_[2], Bh_[3]);
                    mma_bf16(acc[0][2 * jp + 1], (const u32*)&AhA, Bl_[2], Bl_[3]);
                    mma_bf16(acc[0][2 * jp + 1], (const u32*)&AlA, Bh_[2], Bh_[3]);
                    mma_bf16(acc[1][2 * jp],     (const u32*)&AhB, Bh_[0], Bh_[1]);
                    mma_bf16(acc[1][2 * jp],     (const u32*)&AhB, Bl_[0], Bl_[1]);
                    mma_bf16(acc[1][2 * jp],     (const u32*)&AlB, Bh_[0], Bh_[1]);
                    mma_bf16(acc[1][2 * jp + 1], (const u32*)&AhB, Bh_[2], Bh_[3]);
                    mma_bf16(acc[1][2 * jp + 1], (const u32*)&AhB, Bl_[2], Bl_[3]);
                    mma_bf16(acc[1][2 * jp + 1], (const u32*)&AlB, Bh_[2], Bh_[3]);
                }
            }
        }

#pragma unroll
        for (int m = 0; m < 2; m++) {
            const int m0 = mp3 * 32 + m * 16;
            const float bi0 = b3[m0 + g2], bi1 = b3[m0 + g2 + 8];
            float s0 = 0.f, s1 = 0.f;
#pragma unroll
            for (int jl = 0; jl < 8; jl++) {
                float a0 = fmaxf(acc[m][jl][0] + bi0, 0.f);
                float a1 = fmaxf(acc[m][jl][1] + bi0, 0.f);
                s0 += fmaxf(a0, a1);
                float c0 = fmaxf(acc[m][jl][2] + bi1, 0.f);
                float c1 = fmaxf(acc[m][jl][3] + bi1, 0.f);
                s1 += fmaxf(c0, c1);
            }
            s0 += __shfl_xor_sync(0xFFFFFFFFu, s0, 1);
            s0 += __shfl_xor_sync(0xFFFFFFFFu, s0, 2);
            s1 += __shfl_xor_sync(0xFFFFFFFFu, s1, 1);
            s1 += __shfl_xor_sync(0xFFFFFFFFu, s1, 2);
            if (tc == 0) {
                part[(m0 + g2) * 2 + jb3]     = s0;
                part[(m0 + g2 + 8) * 2 + jb3] = s1;
            }
        }
        __syncthreads();
        if (tid < 256) {
            g_feat[(size_t)n * 256 + tid] = (part[2 * tid] + part[2 * tid + 1]) * (1.f / 64.f);
        }
        __syncthreads();
    }
}

// ---------------- fc weight transpose ----------------
__global__ void k_fcT(const float* __restrict__ fcw) {
    int idx = blockIdx.x * blockDim.x + threadIdx.x;
    if (idx < 128 * 256) {
        int j = idx / 256, k = idx % 256;
        g_fcwT[k * 128 + j] = fcw[idx];
    }
}

// ---------------- fc + relu + bn (z -> fp16 split) ----------------
__global__ void k_fc(const float* __restrict__ fcb, const float* __restrict__ gamma,
                     const float* __restrict__ beta, const float* __restrict__ mean,
                     const float* __restrict__ var) {
    const int n = blockIdx.x;
    const int j = threadIdx.x;
    __shared__ float fs[256];
    __shared__ float ps[4];
    fs[j]       = g_feat[(size_t)n * 256 + j];
    fs[j + 128] = g_feat[(size_t)n * 256 + 128 + j];
    __syncthreads();
    float acc = fcb[j];
#pragma unroll 8
    for (int k = 0; k < 256; k++) acc = fmaf(fs[k], g_fcwT[k * 128 + j], acc);
    acc = fmaxf(acc, 0.f);
    float z = gamma[j] * (acc - mean[j]) * rsqrtf(var[j] + 1e-5f) + beta[j];
    u16 zh, zl; hsplit(z, &zh, &zl);
    g_zh[(size_t)n * 128 + j] = zh;
    g_zl[(size_t)n * 128 + j] = zl;
    float s = z * z;
#pragma unroll
    for (int off = 16; off; off >>= 1) s += __shfl_xor_sync(0xFFFFFFFFu, s, off);
    if ((j & 31) == 0) ps[j >> 5] = s;
    __syncthreads();
    if (j == 0) g_sq[n] = ps[0] + ps[1] + ps[2] + ps[3];
}

// ---------------- pairwise (mma.sync fp16 split, 256x128 tile, 512 threads) ----------------
#define PA_L 69632
#define PB_L 34816
#define PB_OFF 139264
#define PT_SMEM (139264 + 69632)
__global__ void __launch_bounds__(512) k_pair(const int* __restrict__ info, float* __restrict__ out) {
    extern __shared__ __align__(16) char psm[];
    u16* Ash = (u16*)psm;
    u16* Bsh = (u16*)(psm + PB_OFF);
    const int ib = blockIdx.y * 256;
    const int jbb = blockIdx.x * 128;
    const int tid = threadIdx.x;
    const int lane = tid & 31, wp = tid >> 5;

    for (int i = tid; i < 4096; i += 512) {
        int r = i >> 4, c = i & 15;
        *(uint4*)((char*)Ash + r * 272 + c * 16)        = ((const uint4*)(g_zh + (size_t)(ib + r) * 128))[c];
        *(uint4*)((char*)Ash + PA_L + r * 272 + c * 16) = ((const uint4*)(g_zl + (size_t)(ib + r) * 128))[c];
    }
    for (int i = tid; i < 2048; i += 512) {
        int r = i >> 4, c = i & 15;
        *(uint4*)((char*)Bsh + r * 272 + c * 16)        = ((const uint4*)(g_zh + (size_t)(jbb + r) * 128))[c];
        *(uint4*)((char*)Bsh + PB_L + r * 272 + c * 16) = ((const uint4*)(g_zl + (size_t)(jbb + r) * 128))[c];
    }
    __syncthreads();

    const int mh = wp >> 1, nh = wp & 1;
    const int m0base = 32 * mh, jbase = nh * 8;
    const u32 aA = smem_u32(Ash);
    const u32 bB = smem_u32(Bsh);
    const int jA = lane >> 3, rA = lane & 7;
    const int arow = (jA & 1) * 8 + rA;
    const u32 acol = (u32)((jA >> 1) * 16);
    const int q = lane >> 3, rr = lane & 7;
    const int browq = jbase * 8 + 8 * (q >> 1) + rr;
    const u32 bcol = (u32)((q & 1) * 16);

    float acc[2][8][4];
#pragma unroll
    for (int m = 0; m < 2; m++)
#pragma unroll
        for (int j = 0; j < 8; j++) { acc[m][j][0] = acc[m][j][1] = acc[m][j][2] = acc[m][j][3] = 0.f; }

#pragma unroll
    for (int kt = 0; kt < 8; kt++) {
        u32 Ah_[2][4], Al_[2][4];
#pragma unroll
        for (int mi = 0; mi < 2; mi++) {
            u32 aad = aA + (u32)(m0base + mi * 16 + arow) * 272u + (u32)(kt * 32) + acol;
            ldsm4(Ah_[mi], aad);
            ldsm4(Al_[mi], aad + PA_L);
        }
#pragma unroll
        for (int jp = 0; jp < 4; jp++) {
            u32 bad = bB + (u32)(browq + jp * 16) * 272u + (u32)(kt * 32) + bcol;
            u32 Bh_[4], Bl_[4];
            ldsm4(Bh_, bad);
            ldsm4(Bl_, bad + PB_L);
#pragma unroll
            for (int mi = 0; mi < 2; mi++) {
                mma_f16(acc[mi][2 * jp],     Ah_[mi], Bh_[0], Bh_[1]);
                mma_f16(acc[mi][2 * jp],     Ah_[mi], Bl_[0], Bl_[1]);
                mma_f16(acc[mi][2 * jp],     Al_[mi], Bh_[0], Bh_[1]);
                mma_f16(acc[mi][2 * jp + 1], Ah_[mi], Bh_[2], Bh_[3]);
                mma_f16(acc[mi][2 * jp + 1], Ah_[mi], Bl_[2], Bl_[3]);
                mma_f16(acc[mi][2 * jp + 1], Al_[mi], Bh_[2], Bh_[3]);
            }
        }
    }

    const int g2 = lane >> 2, tc = lane & 3;
#pragma unroll
    for (int mi = 0; mi < 2; mi++) {
#pragma unroll
        for (int rh = 0; rh < 2; rh++) {
            const int i = ib + m0base + mi * 16 + g2 + rh * 8;
            const float sqi = g_sq[i];
            const int wti = info[2 * i], gi = info[2 * i + 1];
#pragma unroll
            for (int jl = 0; jl < 8; jl++) {
                const int j0 = jbb + nh * 64 + 8 * jl + 2 * tc;
                float c0 = acc[mi][jl][2 * rh], c1 = acc[mi][jl][2 * rh + 1];
                float2 res;
                {
                    float d2 = sqi + g_sq[j0] - 2.f * c0;
                    float d = sqrtf(fmaxf(d2, 0.f));
                    bool y = (wti == info[2 * j0]) && (gi == 1) && (info[2 * j0 + 1] == 1);
                    float cl = y ? d : fmaxf(1.f - d, 0.f);
                    res.x = (i == j0) ? 0.f : cl;
                }
                {
                    int j1 = j0 + 1;
                    float d2 = sqi + g_sq[j1] - 2.f * c1;
                    float d = sqrtf(fmaxf(d2, 0.f));
                    bool y = (wti == info[2 * j1]) && (gi == 1) && (info[2 * j1 + 1] == 1);
                    float cl = y ? d : fmaxf(1.f - d, 0.f);
                    res.y = (i == j1) ? 0.f : cl;
                }
                *reinterpret_cast<float2*>(out + (size_t)i * 4096 + j0) = res;
            }
        }
    }
}

// ---------------- launch ----------------
extern "C" void kernel_launch(void* const* d_in, const int* in_sizes, int n_in,
                              void* d_out, int out_size) {
    const float* samples = (const float*)d_in[0];
    const int*   info    = (const int*)d_in[1];
    const float* w1  = (const float*)d_in[2];
    const float* b1  = (const float*)d_in[3];
    const float* w2  = (const float*)d_in[4];
    const float* b2  = (const float*)d_in[5];
    const float* w3  = (const float*)d_in[6];
    const float* b3  = (const float*)d_in[7];
    const float* fcw = (const float*)d_in[8];
    const float* fcb = (const float*)d_in[9];
    const float* gam = (const float*)d_in[10];
    const float* bet = (const float*)d_in[11];
    const float* bmu = (const float*)d_in[12];
    const float* bva = (const float*)d_in[13];
    float* out = (float*)d_out;

    cudaFuncSetAttribute(k_conv1,  cudaFuncAttributeMaxDynamicSharedMemorySize, C1T_SMEM);
    cudaFuncSetAttribute(k_conv23, cudaFuncAttributeMaxDynamicSharedMemorySize, P_SMEM);
    cudaFuncSetAttribute(k_pair,   cudaFuncAttributeMaxDynamicSharedMemorySize, PT_SMEM);

    k_prep_w1<<<4, 256>>>(w1);
    k_prep_w2<<<20, 256>>>(w2);
    k_prep_w3<<<48, 256>>>(w3);
    k_fcT<<<64, 512>>>(fcw);
    k_conv1<<<dim3(NSAMP, 2), 512, C1T_SMEM>>>(samples, b1);
    k_conv23<<<NPERS, 512, P_SMEM>>>(b2, b3);
    k_fc<<<NSAMP, 128>>>(fcb, gam, bet, bmu, bva);
    k_pair<<<dim3(32, 16), 512, PT_SMEM>>>(info, out);
}